// round 13
// baseline (speedup 1.0000x reference)
#include <cuda_runtime.h>
#include <cuda_fp16.h>
#include <cstdint>
#include <cmath>

// Problem constants
#define EMB    1024
#define DIN    2048      // 2*EMB
#define HDIM   2048      // H
#define G4     8192      // 4*H
#define BB     1024      // batch
#define NSTEP  5
#define PATHL  11

// ---------------------------------------------------------------------------
// Fragment-major layouts (all k16 chunks for mma.m16n8k16.f16):
// A [M][K]h:  tile (mt=row/16, ct=k/16) = 128 u32. Lane l=lg*4+lt owns 4
//   contiguous u32 (16B): q0=(r=lg,u=lt) q1=(lg+8,lt) q2=(lg,lt+4) q3=(lg+8,lt+4)
//   where u = (k/2)%8 is the u32 col in chunk. off = (mt*NC+ct)*128 + l*4 + q.
// B [K][N]h:  tile (nt=n/8, ct=kpair/8) = 64 u32. Lane l owns 2 u32 (8B):
//   q0=(n=lg, kp=lt), q1=(n=lg, kp=lt+4). off = (nt*NC+ct)*64 + l*2 + q.
// NC = K/16.
// ---------------------------------------------------------------------------

// Scratch (device globals: allocation-free, graph-capture safe)
__device__ uint32_t g_Xq [NSTEP * BB * DIN / 2];  // X fragment-major (afrag)
__device__ uint32_t g_Wp [(DIN  / 2) * G4];       // W_lstm bfrag
__device__ uint32_t g_Up [(HDIM / 2) * G4];       // U_lstm bfrag
__device__ uint32_t g_W1p[(HDIM / 2) * DIN];      // W1 bfrag
__device__ uint32_t g_W2p[(DIN  / 2) * DIN];      // W2 bfrag
__device__ float    g_XW [NSTEP * BB * G4];       // X @ W_lstm + b (fp32)
__device__ float    g_Z  [BB * G4];
__device__ uint32_t g_hq [BB * HDIM / 2];         // h afrag (fp16)
__device__ float    g_c  [BB * HDIM];
__device__ uint32_t g_A1q[BB * DIN / 2];          // relu MLP1 out, afrag fp16
__device__ float    g_A2 [BB * DIN];              // relu MLP2 out (fp32)

// ---------------------------------------------------------------------------
// Helpers
// ---------------------------------------------------------------------------
__device__ __forceinline__ uint32_t smem_u32(const void* p) {
    return (uint32_t)__cvta_generic_to_shared(p);
}

#define CP_ASYNC16(dst_u32, src_ptr)                                          \
    asm volatile("cp.async.cg.shared.global [%0], [%1], 16;\n"                \
                 :: "r"(dst_u32), "l"(src_ptr) : "memory")
#define CP_COMMIT()  asm volatile("cp.async.commit_group;\n" ::: "memory")
#define CP_WAIT(n)   asm volatile("cp.async.wait_group %0;\n" :: "n"(n) : "memory")

#define MMA_F16(d, a, b)                                                      \
    asm volatile("mma.sync.aligned.m16n8k16.row.col.f32.f16.f16.f32 "         \
                 "{%0,%1,%2,%3}, {%4,%5,%6,%7}, {%8,%9}, {%0,%1,%2,%3};\n"    \
                 : "+f"((d)[0]), "+f"((d)[1]), "+f"((d)[2]), "+f"((d)[3])     \
                 : "r"((a)[0]), "r"((a)[1]), "r"((a)[2]), "r"((a)[3]),        \
                   "r"((b)[0]), "r"((b)[1]))

__device__ __forceinline__ uint32_t pack_half2(float x, float y) {
    __half2 h = __floats2half2_rn(x, y);
    return *(const uint32_t*)&h;
}

// ---------------------------------------------------------------------------
// 1) Gather -> X afrag: row tb = t*BB+b; u32 col u<512 from emb[p1], else p2
// ---------------------------------------------------------------------------
__global__ void gather_kernel(const int* __restrict__ path,
                              const float* __restrict__ emb)
{
    int tb = blockIdx.x;            // t*1024 + b
    int t  = tb >> 10;
    int b  = tb & 1023;
    int p1 = path[b * PATHL + 1 + 2 * t];
    int p2 = path[b * PATHL + 2 + 2 * t];
    const float2* s1 = (const float2*)(emb + (size_t)p1 * EMB);
    const float2* s2 = (const float2*)(emb + (size_t)p2 * EMB);
    const int mt = tb >> 4, rt = tb & 15;
    const int lg = rt & 7, hi = rt >> 3;
    const int NC = DIN / 16;   // 128
    for (int u = threadIdx.x; u < DIN / 2; u += blockDim.x) {
        float2 f = (u < EMB / 2) ? s1[u] : s2[u - EMB / 2];
        int ct = u >> 3, kc = u & 7;
        size_t off = ((size_t)(mt * NC + ct) * 128)
                   + (lg * 4 + (kc & 3)) * 4 + hi + 2 * (kc >> 2);
        g_Xq[off] = pack_half2(f.x, f.y);
    }
}

// ---------------------------------------------------------------------------
// 2) Pack weights: W[K][N] f32 -> bfrag u32
// ---------------------------------------------------------------------------
__global__ void pack_w(const float* __restrict__ W, uint32_t* __restrict__ Wp,
                       int K, int N)
{
    int idx = blockIdx.x * blockDim.x + threadIdx.x;
    if (idx >= (K / 2) * N) return;
    int kp = idx / N;
    int n  = idx - kp * N;
    float f0 = W[(size_t)(2 * kp)     * N + n];
    float f1 = W[(size_t)(2 * kp + 1) * N + n];
    int NC = K / 16;
    int nt = n >> 3, lg = n & 7, ct = kp >> 3, kc = kp & 7;
    size_t off = ((size_t)(nt * NC + ct) * 64)
               + (lg * 4 + (kc & 3)) * 2 + (kc >> 2);
    Wp[off] = pack_half2(f0, f1);
}

// ---------------------------------------------------------------------------
// 3) FP16 GEMM, fragment-major operands.
//    mode 0: +bias f32 row-major   mode 1: +addmat f32 row-major
//    mode 2: relu(+bias) -> afrag fp16    mode 3: relu(+bias) f32 row-major
//    M%128==0, N%128==0, K%64==0. 256 threads, 8 warps (2M x 4N), warp 64x32.
//    3-stage cp.async ring, BK=64 (4 chunks), frag double buffer, stage-wait
//    folded into chunk 3 (R3 pipeline). Frag loads: 4xLDS.128 + 4xLDS.64.
// ---------------------------------------------------------------------------
#define BM 128
#define BN 128
#define BK 64
#define STAGES 3
#define A_STAGE_U 4096     // 8 m-tiles * 4 chunks * 128 u32 (16KB)
#define B_STAGE_U 4096     // 16 n-tiles * 4 chunks * 64 u32 (16KB)
#define SMEM_BYTES (STAGES * (A_STAGE_U + B_STAGE_U) * 4)   // 98,304 B

__global__ __launch_bounds__(256, 2)
void gemm_f16(const uint32_t* __restrict__ Aq, const uint32_t* __restrict__ Bq,
              const float* __restrict__ bias, const float* __restrict__ addmat,
              void* __restrict__ Cv, int M, int N, int K, int mode)
{
    extern __shared__ uint32_t sm[];
    uint32_t* As = sm;
    uint32_t* Bs = sm + STAGES * A_STAGE_U;

    const int tid  = threadIdx.x;
    const int warp = tid >> 5;
    const int lane = tid & 31;
    const int wm   = (warp & 1) * 64;
    const int wn   = (warp >> 1) * 32;
    const int mtb  = wm >> 4;        // 0 or 4
    const int ntb  = wn >> 3;        // 0,4,8,12
    const int lg   = lane >> 2;
    const int lt   = lane & 3;
    const int bm   = blockIdx.y * BM;
    const int bn   = blockIdx.x * BN;
    const int NC   = K >> 4;         // chunks along K

    const uint32_t sAu = smem_u32(As);
    const uint32_t sBu = smem_u32(Bs);

    // A: thread t copies 4x16B of m-tile (t>>5); piece = 4 chunks = 2KB contig
    // B: thread t copies 4x16B of n-tile (t>>4); piece = 4 chunks = 1KB contig
    const int a_mtl = tid >> 5, a_off = (tid & 31) * 64;  // bytes in piece
    const int b_ntl = tid >> 4, b_off = (tid & 15) * 64;
    const uint32_t* gA0 = Aq + ((size_t)((bm >> 4) + a_mtl) * NC) * 128;
    const uint32_t* gB0 = Bq + ((size_t)((bn >> 3) + b_ntl) * NC) * 64;

    auto load_stage = [&](int slot, int ct0) {
        uint32_t ab = sAu + (uint32_t)slot * (A_STAGE_U * 4);
        uint32_t bb = sBu + (uint32_t)slot * (B_STAGE_U * 4);
        const char* asrc = (const char*)(gA0 + (size_t)ct0 * 128) + a_off;
        const char* bsrc = (const char*)(gB0 + (size_t)ct0 * 64)  + b_off;
        uint32_t ad = ab + (uint32_t)a_mtl * 2048 + a_off;
        uint32_t bd = bb + (uint32_t)b_ntl * 1024 + b_off;
        #pragma unroll
        for (int c = 0; c < 4; c++) {
            CP_ASYNC16(ad + c * 16, asrc + c * 16);
            CP_ASYNC16(bd + c * 16, bsrc + c * 16);
        }
    };

    uint32_t afr[2][4][4];
    uint32_t bfr[2][4][2];

    auto load_frags = [&](uint32_t (*af)[4], uint32_t (*bf)[2],
                          const uint32_t* cA, const uint32_t* cB, int c) {
        #pragma unroll
        for (int i = 0; i < 4; i++) {
            uint4 v = *(const uint4*)(cA + ((mtb + i) * 4 + c) * 128 + lane * 4);
            af[i][0] = v.x; af[i][1] = v.y; af[i][2] = v.z; af[i][3] = v.w;
        }
        #pragma unroll
        for (int j = 0; j < 4; j++) {
            uint2 v = *(const uint2*)(cB + ((ntb + j) * 4 + c) * 64 + lane * 2);
            bf[j][0] = v.x; bf[j][1] = v.y;
        }
    };

    float acc[4][4][4];
    #pragma unroll
    for (int i = 0; i < 4; i++)
        #pragma unroll
        for (int j = 0; j < 4; j++)
            #pragma unroll
            for (int q = 0; q < 4; q++) acc[i][j][q] = 0.0f;

    const int NT = K / BK;   // stages of 4 chunks

    load_stage(0, 0); CP_COMMIT();
    load_stage(1, 4); CP_COMMIT();
    CP_WAIT(1);
    __syncthreads();
    load_frags(afr[0], bfr[0], As, Bs, 0);

    for (int kt = 0; kt < NT; kt++) {
        if (kt + 2 < NT) load_stage((kt + 2) % STAGES, (kt + 2) * 4);
        CP_COMMIT();
        const uint32_t* cA = As + (kt % STAGES) * A_STAGE_U;
        const uint32_t* cB = Bs + (kt % STAGES) * B_STAGE_U;
        #pragma unroll
        for (int kk = 0; kk < 4; kk++) {
            const int cur = kk & 1;
            const int nxt = cur ^ 1;
            if (kk < 3) {
                load_frags(afr[nxt], bfr[nxt], cA, cB, kk + 1);
            } else if (kt + 1 < NT) {
                CP_WAIT(1);          // stage kt+1 resident
                __syncthreads();     // everyone done reading slot kt
                const uint32_t* nA = As + ((kt + 1) % STAGES) * A_STAGE_U;
                const uint32_t* nB = Bs + ((kt + 1) % STAGES) * B_STAGE_U;
                load_frags(afr[nxt], bfr[nxt], nA, nB, 0);
            }
            #pragma unroll
            for (int i = 0; i < 4; i++)
                #pragma unroll
                for (int j = 0; j < 4; j++)
                    MMA_F16(acc[i][j], afr[cur][i], bfr[cur][j]);
        }
    }

    // Epilogue
    const int NCc = N >> 4;   // chunks along N (afrag output)
    #pragma unroll
    for (int i = 0; i < 4; i++) {
        #pragma unroll
        for (int j = 0; j < 4; j++) {
            const int r0 = bm + wm + i * 16 + lg;
            const int c0 = bn + wn + j * 8 + lt * 2;
            #pragma unroll
            for (int h = 0; h < 2; h++) {        // rows r0, r0+8
                const int r = r0 + h * 8;
                float vx = acc[i][j][h * 2 + 0];
                float vy = acc[i][j][h * 2 + 1];
                if (mode == 0) {
                    vx += bias[c0]; vy += bias[c0 + 1];
                    *(float2*)((float*)Cv + (size_t)r * N + c0) = make_float2(vx, vy);
                } else if (mode == 1) {
                    const float2 av = *(const float2*)(addmat + (size_t)r * N + c0);
                    vx += av.x; vy += av.y;
                    *(float2*)((float*)Cv + (size_t)r * N + c0) = make_float2(vx, vy);
                } else if (mode == 2) {
                    vx = fmaxf(vx + bias[c0],     0.0f);
                    vy = fmaxf(vy + bias[c0 + 1], 0.0f);
                    // afrag store: one u32 = half2 (cols c0,c0+1) at (r, k=c0)
                    int mt = r >> 4;             // rt&7 == lg, rt>>3 == h
                    int ct = c0 >> 4;
                    int kc = (c0 >> 1) & 7;
                    size_t off = ((size_t)(mt * NCc + ct) * 128)
                               + (lg * 4 + (kc & 3)) * 4 + h + 2 * (kc >> 2);
                    ((uint32_t*)Cv)[off] = pack_half2(vx, vy);
                } else {
                    vx = fmaxf(vx + bias[c0],     0.0f);
                    vy = fmaxf(vy + bias[c0 + 1], 0.0f);
                    *(float2*)((float*)Cv + (size_t)r * N + c0) = make_float2(vx, vy);
                }
            }
        }
    }
}

// ---------------------------------------------------------------------------
// 4) LSTM cell: gates from Z fp32; writes h into afrag (fp16 halves) + c fp32
// ---------------------------------------------------------------------------
__global__ void lstm_cell(const float* __restrict__ Z, int first)
{
    int idx = blockIdx.x * blockDim.x + threadIdx.x;
    if (idx >= BB * HDIM) return;
    int b = idx >> 11;
    int j = idx & 2047;
    const float* zr = Z + (size_t)b * G4;
    float zi = zr[j];
    float zf = zr[j + HDIM];
    float zg = zr[j + 2 * HDIM];
    float zo = zr[j + 3 * HDIM];
    float ig = 1.0f / (1.0f + expf(-zi));
    float fg = 1.0f / (1.0f + expf(-zf));
    float gg = tanhf(zg);
    float og = 1.0f / (1.0f + expf(-zo));
    float cp = first ? 0.0f : g_c[idx];
    float cn = fg * cp + ig * gg;
    g_c[idx] = cn;
    float hv = og * tanhf(cn);
    // afrag half store: row b, k=j
    int mt = b >> 4, rt = b & 15;
    int lg = rt & 7, hi = rt >> 3;
    int ct = j >> 4, kc = (j >> 1) & 7;
    size_t off = ((size_t)(mt * (HDIM / 16) + ct) * 128)
               + (lg * 4 + (kc & 3)) * 4 + hi + 2 * (kc >> 2);
    ((__half*)g_hq)[off * 2 + (j & 1)] = __float2half(hv);
}

// ---------------------------------------------------------------------------
// 5) Head: logits = A2 @ W3 + b3 (N=2), softmax
// ---------------------------------------------------------------------------
__global__ void head_kernel(const float* __restrict__ W3,
                            const float* __restrict__ b3,
                            float* __restrict__ out)
{
    int b = blockIdx.x;
    const float* a = g_A2 + (size_t)b * DIN;
    float p0 = 0.0f, p1 = 0.0f;
    for (int k = threadIdx.x; k < DIN; k += blockDim.x) {
        float av = a[k];
        p0 += av * W3[k * 2 + 0];
        p1 += av * W3[k * 2 + 1];
    }
    #pragma unroll
    for (int o = 16; o > 0; o >>= 1) {
        p0 += __shfl_down_sync(0xFFFFFFFFu, p0, o);
        p1 += __shfl_down_sync(0xFFFFFFFFu, p1, o);
    }
    __shared__ float r0[8], r1[8];
    int warp = threadIdx.x >> 5, lane = threadIdx.x & 31;
    if (lane == 0) { r0[warp] = p0; r1[warp] = p1; }
    __syncthreads();
    if (threadIdx.x == 0) {
        float l0 = b3[0], l1 = b3[1];
        #pragma unroll
        for (int w = 0; w < 8; w++) { l0 += r0[w]; l1 += r1[w]; }
        float m = fmaxf(l0, l1);
        float e0 = expf(l0 - m), e1 = expf(l1 - m);
        float inv = 1.0f / (e0 + e1);
        out[b * 2 + 0] = e0 * inv;
        out[b * 2 + 1] = e1 * inv;
    }
}

// ---------------------------------------------------------------------------
// Launch
// ---------------------------------------------------------------------------
extern "C" void kernel_launch(void* const* d_in, const int* in_sizes, int n_in,
                              void* d_out, int out_size)
{
    (void)in_sizes; (void)n_in; (void)out_size;
    const int*   path   = (const int*)  d_in[0];
    const float* emb    = (const float*)d_in[1];
    const float* W_lstm = (const float*)d_in[2];
    const float* U_lstm = (const float*)d_in[3];
    const float* b_lstm = (const float*)d_in[4];
    const float* W1     = (const float*)d_in[5];
    const float* b1     = (const float*)d_in[6];
    const float* W2     = (const float*)d_in[7];
    const float* b2     = (const float*)d_in[8];
    const float* W3     = (const float*)d_in[9];
    const float* b3     = (const float*)d_in[10];
    float* out = (float*)d_out;

    uint32_t *Xq, *Wp, *Up, *W1p, *W2p, *hq, *A1q;
    float *XW, *Z, *A2;
    cudaGetSymbolAddress((void**)&Xq,  g_Xq);
    cudaGetSymbolAddress((void**)&Wp,  g_Wp);
    cudaGetSymbolAddress((void**)&Up,  g_Up);
    cudaGetSymbolAddress((void**)&W1p, g_W1p);
    cudaGetSymbolAddress((void**)&W2p, g_W2p);
    cudaGetSymbolAddress((void**)&XW,  g_XW);
    cudaGetSymbolAddress((void**)&Z,   g_Z);
    cudaGetSymbolAddress((void**)&hq,  g_hq);
    cudaGetSymbolAddress((void**)&A1q, g_A1q);
    cudaGetSymbolAddress((void**)&A2,  g_A2);

    cudaFuncSetAttribute(gemm_f16, cudaFuncAttributeMaxDynamicSharedMemorySize,
                         SMEM_BYTES);

    // 1) gather (afrag) + pack all weights (bfrag)
    gather_kernel<<<NSTEP * BB, 256>>>(path, emb);
    pack_w<<<((DIN / 2) * G4 + 255) / 256, 256>>>(W_lstm, Wp,  DIN,  G4);
    pack_w<<<((HDIM / 2) * G4 + 255) / 256, 256>>>(U_lstm, Up,  HDIM, G4);
    pack_w<<<((HDIM / 2) * DIN + 255) / 256, 256>>>(W1,    W1p, HDIM, DIN);
    pack_w<<<((DIN / 2) * DIN + 255) / 256, 256>>>(W2,     W2p, DIN,  DIN);

    // 2) XW = X @ W_lstm + b_lstm  (M=5120, N=8192, K=2048)
    gemm_f16<<<dim3(G4 / BN, (NSTEP * BB) / BM), 256, SMEM_BYTES>>>(
        Xq, Wp, b_lstm, nullptr, XW, NSTEP * BB, G4, DIN, 0);

    // 3) step 0 (h=0): cell directly on XW[0]
    lstm_cell<<<(BB * HDIM) / 256, 256>>>(XW, 1);

    // 4) steps 1..4: Z = h @ U_lstm + XW[t]; cell
    for (int t = 1; t < NSTEP; t++) {
        gemm_f16<<<dim3(G4 / BN, BB / BM), 256, SMEM_BYTES>>>(
            hq, Up, nullptr, XW + (size_t)t * BB * G4, Z, BB, G4, HDIM, 1);
        lstm_cell<<<(BB * HDIM) / 256, 256>>>(Z, 0);
    }

    // 5) MLP: A1q = relu(h@W1+b1) afrag fp16; A2 = relu(A1@W2+b2) f32
    gemm_f16<<<dim3(DIN / BN, BB / BM), 256, SMEM_BYTES>>>(
        hq,  W1p, b1, nullptr, A1q, BB, DIN, HDIM, 2);
    gemm_f16<<<dim3(DIN / BN, BB / BM), 256, SMEM_BYTES>>>(
        A1q, W2p, b2, nullptr, A2,  BB, DIN, DIN, 3);

    // 6) head + softmax
    head_kernel<<<BB, 256>>>(W3, b3, out);
}

// round 15
// speedup vs baseline: 1.0911x; 1.0911x over previous
#include <cuda_runtime.h>
#include <cuda_fp16.h>
#include <cstdint>
#include <cmath>

// Problem constants
#define EMB    1024
#define DIN    2048      // 2*EMB
#define HDIM   2048      // H
#define G4     8192      // 4*H
#define BB     1024      // batch
#define NSTEP  5
#define PATHL  11

// ---------------------------------------------------------------------------
// Scratch (device globals: allocation-free, graph-capture safe)
// Gate matrices (W_lstm, U_lstm) are packed with INTERLEAVED columns:
//   permuted col n' = 4*j + g  <->  original col g*HDIM + j
// so XW and the U-GEMM output hold each hidden unit's (i,f,g,o) adjacently,
// letting the U-GEMM epilogue compute the LSTM cell in-register (no Z buffer).
// h is DOUBLE-BUFFERED: the fused U-GEMM reads h(t-1) from one buffer and
// writes h(t) to the other (cross-CTA hazard otherwise: early CTAs' epilogue
// writes would corrupt the A-operand still being streamed by late CTAs).
// ---------------------------------------------------------------------------
__device__ __half   g_Xh [NSTEP * BB * DIN];      // gathered inputs (fp16)
__device__ uint32_t g_Wp [(DIN  / 2) * G4];       // W_lstm packed (gate-ilv)
__device__ uint32_t g_Up [(HDIM / 2) * G4];       // U_lstm packed (gate-ilv)
__device__ uint32_t g_W1p[(HDIM / 2) * DIN];      // W1 packed (plain)
__device__ uint32_t g_W2p[(DIN  / 2) * DIN];      // W2 packed (plain)
__device__ float    g_XW [NSTEP * BB * G4];       // X @ W_lstm + b (permuted)
__device__ __half   g_hh [BB * HDIM];             // h ping buffer (fp16)
__device__ __half   g_hh2[BB * HDIM];             // h pong buffer (fp16)
__device__ float    g_c  [BB * HDIM];
__device__ __half   g_A1h[BB * DIN];              // relu MLP1 out (fp16)
__device__ float    g_A2 [BB * DIN];              // relu MLP2 out (fp32)

// ---------------------------------------------------------------------------
// Helpers
// ---------------------------------------------------------------------------
__device__ __forceinline__ uint32_t smem_u32(const void* p) {
    return (uint32_t)__cvta_generic_to_shared(p);
}

#define CP_ASYNC16(dst_u32, src_ptr)                                          \
    asm volatile("cp.async.cg.shared.global [%0], [%1], 16;\n"                \
                 :: "r"(dst_u32), "l"(src_ptr) : "memory")
#define CP_COMMIT()  asm volatile("cp.async.commit_group;\n" ::: "memory")
#define CP_WAIT(n)   asm volatile("cp.async.wait_group %0;\n" :: "n"(n) : "memory")

#define MMA_F16(d, a, b)                                                      \
    asm volatile("mma.sync.aligned.m16n8k16.row.col.f32.f16.f16.f32 "         \
                 "{%0,%1,%2,%3}, {%4,%5,%6,%7}, {%8,%9}, {%0,%1,%2,%3};\n"    \
                 : "+f"((d)[0]), "+f"((d)[1]), "+f"((d)[2]), "+f"((d)[3])     \
                 : "r"((a)[0]), "r"((a)[1]), "r"((a)[2]), "r"((a)[3]),        \
                   "r"((b)[0]), "r"((b)[1]))

__device__ __forceinline__ float sigf(float x) {
    return 1.0f / (1.0f + expf(-x));
}

// ---------------------------------------------------------------------------
// 1) Gather (fp32 emb -> fp16 X): X[t*BB+b] = [emb[p1], emb[p2]]
// ---------------------------------------------------------------------------
__global__ void gather_kernel(const int* __restrict__ path,
                              const float* __restrict__ emb)
{
    int tb = blockIdx.x;            // t*1024 + b
    int t  = tb >> 10;
    int b  = tb & 1023;
    int p1 = path[b * PATHL + 1 + 2 * t];
    int p2 = path[b * PATHL + 2 + 2 * t];
    const float4* s1 = (const float4*)(emb + (size_t)p1 * EMB);
    const float4* s2 = (const float4*)(emb + (size_t)p2 * EMB);
    __half2* dst = (__half2*)(g_Xh + (size_t)tb * DIN);
    for (int i = threadIdx.x; i < EMB / 4; i += blockDim.x) {
        float4 v1 = s1[i];
        float4 v2 = s2[i];
        dst[i * 2 + 0]           = __floats2half2_rn(v1.x, v1.y);
        dst[i * 2 + 1]           = __floats2half2_rn(v1.z, v1.w);
        dst[EMB / 2 + i * 2 + 0] = __floats2half2_rn(v2.x, v2.y);
        dst[EMB / 2 + i * 2 + 1] = __floats2half2_rn(v2.z, v2.w);
    }
}

// ---------------------------------------------------------------------------
// 2) Pack weights: W[K][N] fp32 -> Wp[K/2][N] u32 (half2 of k, k+1).
//    perm=1: output col n reads source col (n&3)*HDIM + (n>>2)  (gate ilv).
// ---------------------------------------------------------------------------
__global__ void pack_w(const float* __restrict__ W, uint32_t* __restrict__ Wp,
                       int K, int N, int perm)
{
    int idx = blockIdx.x * blockDim.x + threadIdx.x;
    if (idx >= (K / 2) * N) return;
    int kp = idx / N;
    int n  = idx - kp * N;
    int ns = perm ? ((n & 3) * HDIM + (n >> 2)) : n;
    float f0 = W[(size_t)(2 * kp)     * N + ns];
    float f1 = W[(size_t)(2 * kp + 1) * N + ns];
    __half2 h = __floats2half2_rn(f0, f1);   // .x = k (low), .y = k+1 (high)
    Wp[idx] = *(const uint32_t*)&h;
}

// ---------------------------------------------------------------------------
// 3) FP16 GEMM: C[M,N] = A[M,K] @ B[K,N] (+ epilogue). A fp16 row-major,
//    B pre-packed [K/2][N] u32 (k-pair per reg = exact m16n8k16 B fragment).
//    mode 0: +bias, f32 out           mode 2: relu(+bias), f16 out
//    mode 3: relu(+bias), f32 out
//    mode 4: +bias with gate-interleaved indexing, f32 out  (XW GEMM)
//    mode 5: fused LSTM cell: z = acc + addmat; c updated in-place,
//            h(t) -> hout (DIFFERENT buffer than A).
//    M%128==0, N%128==0, K%64==0. 256 threads, 8 warps (2M x 4N), warp 64x32.
//    3-stage cp.async ring, BK=64, frag double buffer (proven R12 pipeline).
// ---------------------------------------------------------------------------
#define BM 128
#define BN 128
#define BK 64
#define STAGES 3
#define ASTU 36           // A row stride in u32 units (= 72 halves = 144 B)
#define BSTU 136          // B row stride in u32 units (544 B)
#define A_STAGE_U (BM * ASTU)        // 4608 u32
#define B_STAGE_U ((BK / 2) * BSTU)  // 4352 u32
#define SMEM_U32S (STAGES * (A_STAGE_U + B_STAGE_U))
#define SMEM_BYTES (SMEM_U32S * 4)   // 107,520 B

__global__ __launch_bounds__(256, 2)
void gemm_f16(const __half* __restrict__ A, const uint32_t* __restrict__ Bp,
              const float* __restrict__ bias, const float* __restrict__ addmat,
              void* __restrict__ Cv, __half* __restrict__ hout,
              int M, int N, int K, int mode)
{
    extern __shared__ uint32_t sm[];
    uint32_t* As = sm;                       // A tiles, u32 view (2 halves/u32)
    uint32_t* Bs = sm + STAGES * A_STAGE_U;  // B tiles (packed k-pairs)

    const int tid  = threadIdx.x;
    const int warp = tid >> 5;
    const int lane = tid & 31;
    const int wm   = (warp & 1) * 64;
    const int wn   = (warp >> 1) * 32;
    const int lg   = lane >> 2;
    const int lt   = lane & 3;
    const int bm   = blockIdx.y * BM;
    const int bn   = blockIdx.x * BN;

    // global->smem coords
    const int ar = tid >> 1;            // 0..127
    const int acb = (tid & 1) * 4;      // chunk base 0 or 4 (16B chunks)
    const int br = tid >> 3;            // 0..31
    const int bseg = (tid & 7) * 16;    // u32 segment base

    const __half* gA = A + (size_t)(bm + ar) * K;
    const uint32_t sAu = smem_u32(As);
    const uint32_t sBu = smem_u32(Bs);

    auto load_stage = [&](int slot, int k0) {
        uint32_t ab = sAu + (uint32_t)slot * (A_STAGE_U * 4);
        uint32_t bb = sBu + (uint32_t)slot * (B_STAGE_U * 4);
        const __half* a0 = gA + k0;
        const uint32_t* b0 = Bp + (size_t)(k0 / 2 + br) * N + bn + bseg;
        #pragma unroll
        for (int c = 0; c < 4; c++) {
            int ch = acb + c;           // 16B chunk index within row (0..7)
            CP_ASYNC16(ab + (uint32_t)(ar * (ASTU * 4) + ch * 16),
                       a0 + ch * 8);
            CP_ASYNC16(bb + (uint32_t)(br * (BSTU * 4) + (bseg + c * 4) * 4),
                       b0 + c * 4);
        }
    };

    uint32_t afr[2][4][4];
    uint32_t bfr[2][4][2];

    // chunk c covers k = 16c..16c+15
    auto load_frags = [&](uint32_t (*af)[4], uint32_t (*bf)[2],
                          const uint32_t* sA, const uint32_t* sB, int c) {
        #pragma unroll
        for (int i = 0; i < 4; i++) {
            const uint32_t* p = sA + (wm + i * 16 + lg) * ASTU + c * 8 + lt;
            af[i][0] = p[0];
            af[i][1] = p[8 * ASTU];
            af[i][2] = p[4];
            af[i][3] = p[8 * ASTU + 4];
        }
        #pragma unroll
        for (int j = 0; j < 4; j++) {
            const uint32_t* p = sB + (c * 8 + lt) * BSTU + wn + j * 8 + lg;
            bf[j][0] = p[0];
            bf[j][1] = p[4 * BSTU];
        }
    };

    float acc[4][4][4];
    #pragma unroll
    for (int i = 0; i < 4; i++)
        #pragma unroll
        for (int j = 0; j < 4; j++)
            #pragma unroll
            for (int q = 0; q < 4; q++) acc[i][j][q] = 0.0f;

    const int NT = K / BK;

    load_stage(0, 0);  CP_COMMIT();
    load_stage(1, BK); CP_COMMIT();
    CP_WAIT(1);
    __syncthreads();
    load_frags(afr[0], bfr[0], As, Bs, 0);

    for (int kt = 0; kt < NT; kt++) {
        if (kt + 2 < NT) load_stage((kt + 2) % STAGES, (kt + 2) * BK);
        CP_COMMIT();
        const uint32_t* cA = As + (kt % STAGES) * A_STAGE_U;
        const uint32_t* cB = Bs + (kt % STAGES) * B_STAGE_U;
        #pragma unroll
        for (int kk = 0; kk < 4; kk++) {
            const int cur = kk & 1;
            const int nxt = cur ^ 1;
            if (kk < 3) {
                load_frags(afr[nxt], bfr[nxt], cA, cB, kk + 1);
            } else if (kt + 1 < NT) {
                CP_WAIT(1);          // stage kt+1 resident
                __syncthreads();     // everyone done reading slot kt
                const uint32_t* nA = As + ((kt + 1) % STAGES) * A_STAGE_U;
                const uint32_t* nB = Bs + ((kt + 1) % STAGES) * B_STAGE_U;
                load_frags(afr[nxt], bfr[nxt], nA, nB, 0);
            }
            #pragma unroll
            for (int i = 0; i < 4; i++)
                #pragma unroll
                for (int j = 0; j < 4; j++)
                    MMA_F16(acc[i][j], afr[cur][i], bfr[cur][j]);
        }
    }

    // Epilogue
    const int NH = N >> 2;   // hidden width when gate-interleaved
    #pragma unroll
    for (int i = 0; i < 4; i++) {
        #pragma unroll
        for (int j = 0; j < 4; j++) {
            const int r0 = bm + wm + i * 16 + lg;
            const int c0 = bn + wn + j * 8 + lt * 2;
            #pragma unroll
            for (int h = 0; h < 2; h++) {        // rows r0, r0+8
                const int r = r0 + h * 8;
                float vx = acc[i][j][h * 2 + 0];
                float vy = acc[i][j][h * 2 + 1];
                if (mode == 0) {
                    vx += bias[c0]; vy += bias[c0 + 1];
                    *(float2*)((float*)Cv + (size_t)r * N + c0) = make_float2(vx, vy);
                } else if (mode == 2) {
                    vx = fmaxf(vx + bias[c0],     0.0f);
                    vy = fmaxf(vy + bias[c0 + 1], 0.0f);
                    *(__half2*)((__half*)Cv + (size_t)r * N + c0) =
                        __floats2half2_rn(vx, vy);
                } else if (mode == 3) {
                    vx = fmaxf(vx + bias[c0],     0.0f);
                    vy = fmaxf(vy + bias[c0 + 1], 0.0f);
                    *(float2*)((float*)Cv + (size_t)r * N + c0) = make_float2(vx, vy);
                } else if (mode == 4) {
                    // gate-interleaved bias: col c -> bias[(c&3)*HDIM + (c>>2)]
                    vx += bias[((c0    ) & 3) * HDIM + (c0 >> 2)];
                    vy += bias[((c0 + 1) & 3) * HDIM + (c0 >> 2)];
                    *(float2*)((float*)Cv + (size_t)r * N + c0) = make_float2(vx, vy);
                } else {
                    // mode 5: fused LSTM cell. Even lane holds (zi,zf) of
                    // quadruple q=c0>>2; odd lane (lane^1, same row) holds
                    // (zg,zo). Exchange and update c; h -> hout (ping-pong,
                    // never the A buffer).
                    const float2 av = *(const float2*)(addmat + (size_t)r * N + c0);
                    float z0 = vx + av.x;
                    float z1 = vy + av.y;
                    float e0 = __shfl_xor_sync(0xFFFFFFFFu, z0, 1);
                    float e1 = __shfl_xor_sync(0xFFFFFFFFu, z1, 1);
                    if (!(lane & 1)) {
                        int q = c0 >> 2;
                        float ig = sigf(z0);
                        float fg = sigf(z1);
                        float gg = tanhf(e0);
                        float og = sigf(e1);
                        float* cbuf = (float*)Cv;
                        size_t off = (size_t)r * NH + q;
                        float cn = fg * cbuf[off] + ig * gg;
                        cbuf[off] = cn;
                        hout[off] = __float2half(og * tanhf(cn));
                    }
                }
            }
        }
    }
}

// ---------------------------------------------------------------------------
// 4) LSTM cell, step 0 only (c_prev = 0): reads permuted XW[0] as float4
// ---------------------------------------------------------------------------
__global__ void lstm_cell0(const float* __restrict__ XW0)
{
    int idx = blockIdx.x * blockDim.x + threadIdx.x;
    if (idx >= BB * HDIM) return;
    int b = idx >> 11;
    int j = idx & 2047;
    float4 z = ((const float4*)(XW0 + (size_t)b * G4))[j];  // i,f,g,o
    float ig = sigf(z.x);
    float gg = tanhf(z.z);
    float og = sigf(z.w);
    float cn = ig * gg;                 // f*0 + i*g
    g_c[idx]  = cn;
    g_hh[idx] = __float2half(og * tanhf(cn));
}

// ---------------------------------------------------------------------------
// 5) Head: logits = A2 @ W3 + b3 (N=2), softmax
// ---------------------------------------------------------------------------
__global__ void head_kernel(const float* __restrict__ W3,
                            const float* __restrict__ b3,
                            float* __restrict__ out)
{
    int b = blockIdx.x;
    const float* a = g_A2 + (size_t)b * DIN;
    float p0 = 0.0f, p1 = 0.0f;
    for (int k = threadIdx.x; k < DIN; k += blockDim.x) {
        float av = a[k];
        p0 += av * W3[k * 2 + 0];
        p1 += av * W3[k * 2 + 1];
    }
    #pragma unroll
    for (int o = 16; o > 0; o >>= 1) {
        p0 += __shfl_down_sync(0xFFFFFFFFu, p0, o);
        p1 += __shfl_down_sync(0xFFFFFFFFu, p1, o);
    }
    __shared__ float r0[8], r1[8];
    int warp = threadIdx.x >> 5, lane = threadIdx.x & 31;
    if (lane == 0) { r0[warp] = p0; r1[warp] = p1; }
    __syncthreads();
    if (threadIdx.x == 0) {
        float l0 = b3[0], l1 = b3[1];
        #pragma unroll
        for (int w = 0; w < 8; w++) { l0 += r0[w]; l1 += r1[w]; }
        float m = fmaxf(l0, l1);
        float e0 = expf(l0 - m), e1 = expf(l1 - m);
        float inv = 1.0f / (e0 + e1);
        out[b * 2 + 0] = e0 * inv;
        out[b * 2 + 1] = e1 * inv;
    }
}

// ---------------------------------------------------------------------------
// Launch
// ---------------------------------------------------------------------------
extern "C" void kernel_launch(void* const* d_in, const int* in_sizes, int n_in,
                              void* d_out, int out_size)
{
    (void)in_sizes; (void)n_in; (void)out_size;
    const int*   path   = (const int*)  d_in[0];
    const float* emb    = (const float*)d_in[1];
    const float* W_lstm = (const float*)d_in[2];
    const float* U_lstm = (const float*)d_in[3];
    const float* b_lstm = (const float*)d_in[4];
    const float* W1     = (const float*)d_in[5];
    const float* b1     = (const float*)d_in[6];
    const float* W2     = (const float*)d_in[7];
    const float* b2     = (const float*)d_in[8];
    const float* W3     = (const float*)d_in[9];
    const float* b3     = (const float*)d_in[10];
    float* out = (float*)d_out;

    __half *hh, *hh2, *A1h, *Xh;
    uint32_t *Wp, *Up, *W1p, *W2p;
    float *XW, *cbuf, *A2;
    cudaGetSymbolAddress((void**)&Xh,  g_Xh);
    cudaGetSymbolAddress((void**)&Wp,  g_Wp);
    cudaGetSymbolAddress((void**)&Up,  g_Up);
    cudaGetSymbolAddress((void**)&W1p, g_W1p);
    cudaGetSymbolAddress((void**)&W2p, g_W2p);
    cudaGetSymbolAddress((void**)&XW,  g_XW);
    cudaGetSymbolAddress((void**)&hh,  g_hh);
    cudaGetSymbolAddress((void**)&hh2, g_hh2);
    cudaGetSymbolAddress((void**)&cbuf, g_c);
    cudaGetSymbolAddress((void**)&A1h, g_A1h);
    cudaGetSymbolAddress((void**)&A2,  g_A2);

    cudaFuncSetAttribute(gemm_f16, cudaFuncAttributeMaxDynamicSharedMemorySize,
                         SMEM_BYTES);

    // 1) gather (fp16) + pack weights (gate matrices interleaved)
    gather_kernel<<<NSTEP * BB, 256>>>(path, emb);
    pack_w<<<((DIN / 2) * G4 + 255) / 256, 256>>>(W_lstm, Wp,  DIN,  G4, 1);
    pack_w<<<((HDIM / 2) * G4 + 255) / 256, 256>>>(U_lstm, Up,  HDIM, G4, 1);
    pack_w<<<((HDIM / 2) * DIN + 255) / 256, 256>>>(W1,    W1p, HDIM, DIN, 0);
    pack_w<<<((DIN / 2) * DIN + 255) / 256, 256>>>(W2,     W2p, DIN,  DIN, 0);

    // 2) XW = X @ W_lstm + b_lstm  (permuted cols; M=5120, N=8192, K=2048)
    gemm_f16<<<dim3(G4 / BN, (NSTEP * BB) / BM), 256, SMEM_BYTES>>>(
        Xh, Wp, b_lstm, nullptr, XW, nullptr, NSTEP * BB, G4, DIN, 4);

    // 3) step 0 (h=0, c=0): cell directly on permuted XW[0] -> h in buf0
    lstm_cell0<<<(BB * HDIM) / 256, 256>>>(XW);

    // 4) steps 1..4: fused  z = h @ U_lstm + XW[t]; cell.
    //    Ping-pong h buffers: read hbuf[cur], write hbuf[cur^1].
    __half* hbuf[2] = {hh, hh2};
    int cur = 0;
    for (int t = 1; t < NSTEP; t++) {
        gemm_f16<<<dim3(G4 / BN, BB / BM), 256, SMEM_BYTES>>>(
            hbuf[cur], Up, nullptr, XW + (size_t)t * BB * G4, cbuf,
            hbuf[cur ^ 1], BB, G4, HDIM, 5);
        cur ^= 1;
    }
    // After 4 steps cur == 0: final h is in hbuf[0] == g_hh.

    // 5) MLP: A1h = relu(h@W1+b1) fp16; A2 = relu(A1@W2+b2) fp32
    gemm_f16<<<dim3(DIN / BN, BB / BM), 256, SMEM_BYTES>>>(
        hbuf[cur], W1p, b1, nullptr, A1h, nullptr, BB, DIN, HDIM, 2);
    gemm_f16<<<dim3(DIN / BN, BB / BM), 256, SMEM_BYTES>>>(
        A1h, W2p, b2, nullptr, A2,  nullptr, BB, DIN, DIN, 3);

    // 6) head + softmax
    head_kernel<<<BB, 256>>>(W3, b3, out);
}

// round 16
// speedup vs baseline: 1.1472x; 1.0515x over previous
#include <cuda_runtime.h>
#include <cuda_fp16.h>
#include <cstdint>
#include <cmath>

// Problem constants
#define EMB    1024
#define DIN    2048      // 2*EMB
#define HDIM   2048      // H
#define G4     8192      // 4*H
#define BB     1024      // batch
#define NSTEP  5
#define PATHL  11
#define LDA    2048      // row stride (halves) of every A source in this net

// ---------------------------------------------------------------------------
// Scratch (device globals: allocation-free, graph-capture safe)
// W_lstm and U_lstm are packed into ONE concatenated B operand of K=4096:
//   kp rows 0..1023  = W_lstm (k 0..2047)
//   kp rows 1024..2047 = U_lstm (k 2048..4095)
// Each step's gate GEMM computes z = [x_t, h_{t-1}] @ [W;U] + b directly
// (dual-source A), so XW is never materialized.
// ---------------------------------------------------------------------------
__device__ __half   g_Xh  [NSTEP * BB * DIN];       // gathered inputs (fp16)
__device__ uint32_t g_WUp [(2 * DIN / 2) * G4];     // [W;U] packed k-pairs (64MB)
__device__ uint32_t g_W1p [(HDIM / 2) * DIN];       // W1 packed
__device__ uint32_t g_W2p [(DIN  / 2) * DIN];       // W2 packed
__device__ float    g_Z   [BB * G4];                // per-step gates (fp32)
__device__ __half   g_hh  [BB * HDIM];              // h (fp16, feeds GEMMs)
__device__ float    g_c   [BB * HDIM];
__device__ __half   g_A1h [BB * DIN];               // relu MLP1 out (fp16)
__device__ float    g_A2  [BB * DIN];               // relu MLP2 out (fp32)

// ---------------------------------------------------------------------------
// Helpers
// ---------------------------------------------------------------------------
__device__ __forceinline__ uint32_t smem_u32(const void* p) {
    return (uint32_t)__cvta_generic_to_shared(p);
}

#define CP_ASYNC16(dst_u32, src_ptr)                                          \
    asm volatile("cp.async.cg.shared.global [%0], [%1], 16;\n"                \
                 :: "r"(dst_u32), "l"(src_ptr) : "memory")
#define CP_COMMIT()  asm volatile("cp.async.commit_group;\n" ::: "memory")
#define CP_WAIT(n)   asm volatile("cp.async.wait_group %0;\n" :: "n"(n) : "memory")

#define MMA_F16(d, a, b)                                                      \
    asm volatile("mma.sync.aligned.m16n8k16.row.col.f32.f16.f16.f32 "         \
                 "{%0,%1,%2,%3}, {%4,%5,%6,%7}, {%8,%9}, {%0,%1,%2,%3};\n"    \
                 : "+f"((d)[0]), "+f"((d)[1]), "+f"((d)[2]), "+f"((d)[3])     \
                 : "r"((a)[0]), "r"((a)[1]), "r"((a)[2]), "r"((a)[3]),        \
                   "r"((b)[0]), "r"((b)[1]))

__device__ __forceinline__ float sigf(float x) {
    return 1.0f / (1.0f + expf(-x));
}

// ---------------------------------------------------------------------------
// 1) Gather (fp32 emb -> fp16 X): X[t*BB+b] = [emb[p1], emb[p2]]
// ---------------------------------------------------------------------------
__global__ void gather_kernel(const int* __restrict__ path,
                              const float* __restrict__ emb)
{
    int tb = blockIdx.x;            // t*1024 + b
    int t  = tb >> 10;
    int b  = tb & 1023;
    int p1 = path[b * PATHL + 1 + 2 * t];
    int p2 = path[b * PATHL + 2 + 2 * t];
    const float4* s1 = (const float4*)(emb + (size_t)p1 * EMB);
    const float4* s2 = (const float4*)(emb + (size_t)p2 * EMB);
    __half2* dst = (__half2*)(g_Xh + (size_t)tb * DIN);
    for (int i = threadIdx.x; i < EMB / 4; i += blockDim.x) {
        float4 v1 = s1[i];
        float4 v2 = s2[i];
        dst[i * 2 + 0]           = __floats2half2_rn(v1.x, v1.y);
        dst[i * 2 + 1]           = __floats2half2_rn(v1.z, v1.w);
        dst[EMB / 2 + i * 2 + 0] = __floats2half2_rn(v2.x, v2.y);
        dst[EMB / 2 + i * 2 + 1] = __floats2half2_rn(v2.z, v2.w);
    }
}

// ---------------------------------------------------------------------------
// 2) Pack weights: W[K][N] fp32 -> Wp[K/2][N] u32 (half2 of k, k+1)
// ---------------------------------------------------------------------------
__global__ void pack_w(const float* __restrict__ W, uint32_t* __restrict__ Wp,
                       int K, int N)
{
    int idx = blockIdx.x * blockDim.x + threadIdx.x;
    if (idx >= (K / 2) * N) return;
    int kp = idx / N;
    int n  = idx - kp * N;
    float f0 = W[(size_t)(2 * kp)     * N + n];
    float f1 = W[(size_t)(2 * kp + 1) * N + n];
    __half2 h = __floats2half2_rn(f0, f1);   // .x = k (low), .y = k+1 (high)
    Wp[idx] = *(const uint32_t*)&h;
}

// ---------------------------------------------------------------------------
// 3) FP16 GEMM: C = [A | Aalt] @ B + epilogue, dual-source A along K.
//    A rows have stride LDA (2048 halves). k < Ksplit reads A, else Aalt
//    (at k-Ksplit). Pass Ksplit=K for single-source.
//    B pre-packed [K/2][N] u32 (k-pair per reg = m16n8k16 B fragment).
//    mode 0: +bias, f32 out    mode 2: relu(+bias), f16 out
//    mode 3: relu(+bias), f32 out
//    M%128==0, N%128==0, K%64==0, Ksplit%64==0.
//    256 threads, 8 warps (2M x 4N), warp 64x32. 3-stage cp.async ring,
//    BK=64, fragment double buffer (proven R12 pipeline, unchanged).
// ---------------------------------------------------------------------------
#define BM 128
#define BN 128
#define BK 64
#define STAGES 3
#define ASTU 36           // A row stride in u32 units (= 72 halves = 144 B)
#define BSTU 136          // B row stride in u32 units (544 B)
#define A_STAGE_U (BM * ASTU)        // 4608 u32
#define B_STAGE_U ((BK / 2) * BSTU)  // 4352 u32
#define SMEM_U32S (STAGES * (A_STAGE_U + B_STAGE_U))
#define SMEM_BYTES (SMEM_U32S * 4)   // 107,520 B

__global__ __launch_bounds__(256, 2)
void gemm_f16(const __half* __restrict__ A, const __half* __restrict__ Aalt,
              int Ksplit, const uint32_t* __restrict__ Bp,
              const float* __restrict__ bias, void* __restrict__ Cv,
              int M, int N, int K, int mode)
{
    extern __shared__ uint32_t sm[];
    uint32_t* As = sm;                       // A tiles, u32 view (2 halves/u32)
    uint32_t* Bs = sm + STAGES * A_STAGE_U;  // B tiles (packed k-pairs)

    const int tid  = threadIdx.x;
    const int warp = tid >> 5;
    const int lane = tid & 31;
    const int wm   = (warp & 1) * 64;
    const int wn   = (warp >> 1) * 32;
    const int lg   = lane >> 2;
    const int lt   = lane & 3;
    const int bm   = blockIdx.y * BM;
    const int bn   = blockIdx.x * BN;

    // global->smem coords
    const int ar = tid >> 1;            // 0..127
    const int acb = (tid & 1) * 4;      // chunk base 0 or 4 (16B chunks)
    const int br = tid >> 3;            // 0..31
    const int bseg = (tid & 7) * 16;    // u32 segment base

    // dual-source A bases (both stride LDA); aB2 pre-shifted by -Ksplit
    const __half* aB1 = A    + (size_t)(bm + ar) * LDA;
    const __half* aB2 = Aalt + (size_t)(bm + ar) * LDA - Ksplit;
    const uint32_t sAu = smem_u32(As);
    const uint32_t sBu = smem_u32(Bs);

    auto load_stage = [&](int slot, int k0) {
        uint32_t ab = sAu + (uint32_t)slot * (A_STAGE_U * 4);
        uint32_t bb = sBu + (uint32_t)slot * (B_STAGE_U * 4);
        const __half* a0 = ((k0 < Ksplit) ? aB1 : aB2) + k0;
        const uint32_t* b0 = Bp + (size_t)(k0 / 2 + br) * N + bn + bseg;
        #pragma unroll
        for (int c = 0; c < 4; c++) {
            int ch = acb + c;           // 16B chunk index within row (0..7)
            CP_ASYNC16(ab + (uint32_t)(ar * (ASTU * 4) + ch * 16),
                       a0 + ch * 8);
            CP_ASYNC16(bb + (uint32_t)(br * (BSTU * 4) + (bseg + c * 4) * 4),
                       b0 + c * 4);
        }
    };

    uint32_t afr[2][4][4];
    uint32_t bfr[2][4][2];

    // chunk c covers k = 16c..16c+15
    auto load_frags = [&](uint32_t (*af)[4], uint32_t (*bf)[2],
                          const uint32_t* sA, const uint32_t* sB, int c) {
        #pragma unroll
        for (int i = 0; i < 4; i++) {
            const uint32_t* p = sA + (wm + i * 16 + lg) * ASTU + c * 8 + lt;
            af[i][0] = p[0];
            af[i][1] = p[8 * ASTU];
            af[i][2] = p[4];
            af[i][3] = p[8 * ASTU + 4];
        }
        #pragma unroll
        for (int j = 0; j < 4; j++) {
            const uint32_t* p = sB + (c * 8 + lt) * BSTU + wn + j * 8 + lg;
            bf[j][0] = p[0];
            bf[j][1] = p[4 * BSTU];
        }
    };

    float acc[4][4][4];
    #pragma unroll
    for (int i = 0; i < 4; i++)
        #pragma unroll
        for (int j = 0; j < 4; j++)
            #pragma unroll
            for (int q = 0; q < 4; q++) acc[i][j][q] = 0.0f;

    const int NT = K / BK;

    load_stage(0, 0);  CP_COMMIT();
    load_stage(1, BK); CP_COMMIT();
    CP_WAIT(1);
    __syncthreads();
    load_frags(afr[0], bfr[0], As, Bs, 0);

    for (int kt = 0; kt < NT; kt++) {
        if (kt + 2 < NT) load_stage((kt + 2) % STAGES, (kt + 2) * BK);
        CP_COMMIT();
        const uint32_t* cA = As + (kt % STAGES) * A_STAGE_U;
        const uint32_t* cB = Bs + (kt % STAGES) * B_STAGE_U;
        #pragma unroll
        for (int kk = 0; kk < 4; kk++) {
            const int cur = kk & 1;
            const int nxt = cur ^ 1;
            if (kk < 3) {
                load_frags(afr[nxt], bfr[nxt], cA, cB, kk + 1);
            } else if (kt + 1 < NT) {
                CP_WAIT(1);          // stage kt+1 resident
                __syncthreads();     // everyone done reading slot kt
                const uint32_t* nA = As + ((kt + 1) % STAGES) * A_STAGE_U;
                const uint32_t* nB = Bs + ((kt + 1) % STAGES) * B_STAGE_U;
                load_frags(afr[nxt], bfr[nxt], nA, nB, 0);
            }
            #pragma unroll
            for (int i = 0; i < 4; i++)
                #pragma unroll
                for (int j = 0; j < 4; j++)
                    MMA_F16(acc[i][j], afr[cur][i], bfr[cur][j]);
        }
    }

    // Epilogue: float2 / half2 stores
    #pragma unroll
    for (int i = 0; i < 4; i++) {
        #pragma unroll
        for (int j = 0; j < 4; j++) {
            const int r0 = bm + wm + i * 16 + lg;
            const int c0 = bn + wn + j * 8 + lt * 2;
            #pragma unroll
            for (int h = 0; h < 2; h++) {        // rows r0, r0+8
                const int r = r0 + h * 8;
                float vx = acc[i][j][h * 2 + 0];
                float vy = acc[i][j][h * 2 + 1];
                if (mode == 0) {
                    vx += bias[c0]; vy += bias[c0 + 1];
                    *(float2*)((float*)Cv + (size_t)r * N + c0) = make_float2(vx, vy);
                } else if (mode == 2) {
                    vx = fmaxf(vx + bias[c0],     0.0f);
                    vy = fmaxf(vy + bias[c0 + 1], 0.0f);
                    *(__half2*)((__half*)Cv + (size_t)r * N + c0) =
                        __floats2half2_rn(vx, vy);
                } else {
                    vx = fmaxf(vx + bias[c0],     0.0f);
                    vy = fmaxf(vy + bias[c0 + 1], 0.0f);
                    *(float2*)((float*)Cv + (size_t)r * N + c0) = make_float2(vx, vy);
                }
            }
        }
    }
}

// ---------------------------------------------------------------------------
// 4) LSTM cell (R12-proven): gates from Z fp32; h -> fp16, c -> fp32
// ---------------------------------------------------------------------------
__global__ void lstm_cell(const float* __restrict__ Z, int first)
{
    int idx = blockIdx.x * blockDim.x + threadIdx.x;
    if (idx >= BB * HDIM) return;
    int b = idx >> 11;
    int j = idx & 2047;
    const float* zr = Z + (size_t)b * G4;
    float zi = zr[j];
    float zf = zr[j + HDIM];
    float zg = zr[j + 2 * HDIM];
    float zo = zr[j + 3 * HDIM];
    float ig = sigf(zi);
    float fg = sigf(zf);
    float gg = tanhf(zg);
    float og = sigf(zo);
    float cp = first ? 0.0f : g_c[idx];
    float cn = fg * cp + ig * gg;
    g_c[idx]  = cn;
    g_hh[idx] = __float2half(og * tanhf(cn));
}

// ---------------------------------------------------------------------------
// 5) Head: logits = A2 @ W3 + b3 (N=2), softmax
// ---------------------------------------------------------------------------
__global__ void head_kernel(const float* __restrict__ W3,
                            const float* __restrict__ b3,
                            float* __restrict__ out)
{
    int b = blockIdx.x;
    const float* a = g_A2 + (size_t)b * DIN;
    float p0 = 0.0f, p1 = 0.0f;
    for (int k = threadIdx.x; k < DIN; k += blockDim.x) {
        float av = a[k];
        p0 += av * W3[k * 2 + 0];
        p1 += av * W3[k * 2 + 1];
    }
    #pragma unroll
    for (int o = 16; o > 0; o >>= 1) {
        p0 += __shfl_down_sync(0xFFFFFFFFu, p0, o);
        p1 += __shfl_down_sync(0xFFFFFFFFu, p1, o);
    }
    __shared__ float r0[8], r1[8];
    int warp = threadIdx.x >> 5, lane = threadIdx.x & 31;
    if (lane == 0) { r0[warp] = p0; r1[warp] = p1; }
    __syncthreads();
    if (threadIdx.x == 0) {
        float l0 = b3[0], l1 = b3[1];
        #pragma unroll
        for (int w = 0; w < 8; w++) { l0 += r0[w]; l1 += r1[w]; }
        float m = fmaxf(l0, l1);
        float e0 = expf(l0 - m), e1 = expf(l1 - m);
        float inv = 1.0f / (e0 + e1);
        out[b * 2 + 0] = e0 * inv;
        out[b * 2 + 1] = e1 * inv;
    }
}

// ---------------------------------------------------------------------------
// Launch
// ---------------------------------------------------------------------------
extern "C" void kernel_launch(void* const* d_in, const int* in_sizes, int n_in,
                              void* d_out, int out_size)
{
    (void)in_sizes; (void)n_in; (void)out_size;
    const int*   path   = (const int*)  d_in[0];
    const float* emb    = (const float*)d_in[1];
    const float* W_lstm = (const float*)d_in[2];
    const float* U_lstm = (const float*)d_in[3];
    const float* b_lstm = (const float*)d_in[4];
    const float* W1     = (const float*)d_in[5];
    const float* b1     = (const float*)d_in[6];
    const float* W2     = (const float*)d_in[7];
    const float* b2     = (const float*)d_in[8];
    const float* W3     = (const float*)d_in[9];
    const float* b3     = (const float*)d_in[10];
    float* out = (float*)d_out;

    __half *Xh, *hh, *A1h;
    uint32_t *WUp, *W1p, *W2p;
    float *Z, *A2;
    cudaGetSymbolAddress((void**)&Xh,  g_Xh);
    cudaGetSymbolAddress((void**)&WUp, g_WUp);
    cudaGetSymbolAddress((void**)&W1p, g_W1p);
    cudaGetSymbolAddress((void**)&W2p, g_W2p);
    cudaGetSymbolAddress((void**)&Z,   g_Z);
    cudaGetSymbolAddress((void**)&hh,  g_hh);
    cudaGetSymbolAddress((void**)&A1h, g_A1h);
    cudaGetSymbolAddress((void**)&A2,  g_A2);

    cudaFuncSetAttribute(gemm_f16, cudaFuncAttributeMaxDynamicSharedMemorySize,
                         SMEM_BYTES);

    // 1) gather (fp16) + pack weights. [W;U] concatenated along K.
    gather_kernel<<<NSTEP * BB, 256>>>(path, emb);
    pack_w<<<((DIN / 2) * G4 + 255) / 256, 256>>>(W_lstm, WUp, DIN, G4);
    pack_w<<<((HDIM / 2) * G4 + 255) / 256, 256>>>(
        U_lstm, WUp + (size_t)(DIN / 2) * G4, HDIM, G4);
    pack_w<<<((HDIM / 2) * DIN + 255) / 256, 256>>>(W1, W1p, HDIM, DIN);
    pack_w<<<((DIN / 2) * DIN + 255) / 256, 256>>>(W2,  W2p, DIN,  DIN);

    const dim3 gGate(G4 / BN, BB / BM);    // 64 x 8

    // 2) step 0 (h=0): z = x_0 @ W + b  (K=2048, single source), then cell
    gemm_f16<<<gGate, 256, SMEM_BYTES>>>(
        Xh, Xh, DIN, WUp, b_lstm, Z, BB, G4, DIN, 0);
    lstm_cell<<<(BB * HDIM) / 256, 256>>>(Z, 1);

    // 3) steps 1..4: z = [x_t, h] @ [W;U] + b  (K=4096, dual source), cell
    for (int t = 1; t < NSTEP; t++) {
        gemm_f16<<<gGate, 256, SMEM_BYTES>>>(
            Xh + (size_t)t * BB * DIN, hh, DIN, WUp, b_lstm, Z,
            BB, G4, 2 * DIN, 0);
        lstm_cell<<<(BB * HDIM) / 256, 256>>>(Z, 0);
    }

    // 4) MLP: A1h = relu(h@W1+b1) fp16; A2 = relu(A1@W2+b2) fp32
    gemm_f16<<<dim3(DIN / BN, BB / BM), 256, SMEM_BYTES>>>(
        hh,  hh,  HDIM, W1p, b1, A1h, BB, DIN, HDIM, 2);
    gemm_f16<<<dim3(DIN / BN, BB / BM), 256, SMEM_BYTES>>>(
        A1h, A1h, DIN,  W2p, b2, A2,  BB, DIN, DIN, 3);

    // 5) head + softmax
    head_kernel<<<BB, 256>>>(W3, b3, out);
}

// round 17
// speedup vs baseline: 1.2305x; 1.0726x over previous
#include <cuda_runtime.h>
#include <cuda_fp16.h>
#include <cstdint>
#include <cmath>

// Problem constants
#define EMB    1024
#define DIN    2048      // 2*EMB
#define HDIM   2048      // H
#define G4     8192      // 4*H
#define BB     1024      // batch
#define NSTEP  5
#define PATHL  11

// ---------------------------------------------------------------------------
// Scratch (device globals: allocation-free, graph-capture safe)
// R12 structure; XW and Z held in fp16 to cut recurrence traffic ~290 MB.
// ---------------------------------------------------------------------------
__device__ __half   g_Xh [NSTEP * BB * DIN];      // gathered inputs (fp16)
__device__ uint32_t g_Wp [(DIN  / 2) * G4];       // W_lstm packed k-pairs
__device__ uint32_t g_Up [(HDIM / 2) * G4];       // U_lstm packed
__device__ uint32_t g_W1p[(HDIM / 2) * DIN];      // W1 packed
__device__ uint32_t g_W2p[(DIN  / 2) * DIN];      // W2 packed
__device__ __half   g_XWh[NSTEP * BB * G4];       // X @ W_lstm + b (fp16)
__device__ __half   g_Zh [BB * G4];               // per-step gates (fp16)
__device__ __half   g_hh [BB * HDIM];             // h (fp16, feeds GEMMs)
__device__ float    g_c  [BB * HDIM];
__device__ __half   g_A1h[BB * DIN];              // relu MLP1 out (fp16)
__device__ float    g_A2 [BB * DIN];              // relu MLP2 out (fp32)

// ---------------------------------------------------------------------------
// Helpers
// ---------------------------------------------------------------------------
__device__ __forceinline__ uint32_t smem_u32(const void* p) {
    return (uint32_t)__cvta_generic_to_shared(p);
}

#define CP_ASYNC16(dst_u32, src_ptr)                                          \
    asm volatile("cp.async.cg.shared.global [%0], [%1], 16;\n"                \
                 :: "r"(dst_u32), "l"(src_ptr) : "memory")
#define CP_COMMIT()  asm volatile("cp.async.commit_group;\n" ::: "memory")
#define CP_WAIT(n)   asm volatile("cp.async.wait_group %0;\n" :: "n"(n) : "memory")

#define MMA_F16(d, a, b)                                                      \
    asm volatile("mma.sync.aligned.m16n8k16.row.col.f32.f16.f16.f32 "         \
                 "{%0,%1,%2,%3}, {%4,%5,%6,%7}, {%8,%9}, {%0,%1,%2,%3};\n"    \
                 : "+f"((d)[0]), "+f"((d)[1]), "+f"((d)[2]), "+f"((d)[3])     \
                 : "r"((a)[0]), "r"((a)[1]), "r"((a)[2]), "r"((a)[3]),        \
                   "r"((b)[0]), "r"((b)[1]))

__device__ __forceinline__ float sigf(float x) {
    return 1.0f / (1.0f + expf(-x));
}

// ---------------------------------------------------------------------------
// 1) Gather (fp32 emb -> fp16 X): X[t*BB+b] = [emb[p1], emb[p2]]
// ---------------------------------------------------------------------------
__global__ void gather_kernel(const int* __restrict__ path,
                              const float* __restrict__ emb)
{
    int tb = blockIdx.x;            // t*1024 + b
    int t  = tb >> 10;
    int b  = tb & 1023;
    int p1 = path[b * PATHL + 1 + 2 * t];
    int p2 = path[b * PATHL + 2 + 2 * t];
    const float4* s1 = (const float4*)(emb + (size_t)p1 * EMB);
    const float4* s2 = (const float4*)(emb + (size_t)p2 * EMB);
    __half2* dst = (__half2*)(g_Xh + (size_t)tb * DIN);
    for (int i = threadIdx.x; i < EMB / 4; i += blockDim.x) {
        float4 v1 = s1[i];
        float4 v2 = s2[i];
        dst[i * 2 + 0]           = __floats2half2_rn(v1.x, v1.y);
        dst[i * 2 + 1]           = __floats2half2_rn(v1.z, v1.w);
        dst[EMB / 2 + i * 2 + 0] = __floats2half2_rn(v2.x, v2.y);
        dst[EMB / 2 + i * 2 + 1] = __floats2half2_rn(v2.z, v2.w);
    }
}

// ---------------------------------------------------------------------------
// 2) Pack weights: W[K][N] fp32 -> Wp[K/2][N] u32 (half2 of k, k+1)
// ---------------------------------------------------------------------------
__global__ void pack_w(const float* __restrict__ W, uint32_t* __restrict__ Wp,
                       int K, int N)
{
    int idx = blockIdx.x * blockDim.x + threadIdx.x;
    if (idx >= (K / 2) * N) return;
    int kp = idx / N;
    int n  = idx - kp * N;
    float f0 = W[(size_t)(2 * kp)     * N + n];
    float f1 = W[(size_t)(2 * kp + 1) * N + n];
    __half2 h = __floats2half2_rn(f0, f1);   // .x = k (low), .y = k+1 (high)
    Wp[idx] = *(const uint32_t*)&h;
}

// ---------------------------------------------------------------------------
// 3) FP16 GEMM: C[M,N] = A[M,K] @ B[K,N] (+ epilogue). A fp16 row-major,
//    B pre-packed [K/2][N] u32 (k-pair per reg = exact m16n8k16 B fragment).
//    mode 0: +bias, f16 out             mode 1: +addmat(f16), f16 out
//    mode 2: relu(+bias), f16 out       mode 3: relu(+bias), f32 out
//    M%128==0, N%128==0, K%64==0. 256 threads, 8 warps (2M x 4N), warp 64x32.
//    3-stage cp.async ring, BK=64, frag double buffer (proven R12 pipeline).
// ---------------------------------------------------------------------------
#define BM 128
#define BN 128
#define BK 64
#define STAGES 3
#define ASTU 36           // A row stride in u32 units (= 72 halves = 144 B)
#define BSTU 136          // B row stride in u32 units (544 B)
#define A_STAGE_U (BM * ASTU)        // 4608 u32
#define B_STAGE_U ((BK / 2) * BSTU)  // 4352 u32
#define SMEM_U32S (STAGES * (A_STAGE_U + B_STAGE_U))
#define SMEM_BYTES (SMEM_U32S * 4)   // 107,520 B

__global__ __launch_bounds__(256, 2)
void gemm_f16(const __half* __restrict__ A, const uint32_t* __restrict__ Bp,
              const float* __restrict__ bias, const __half* __restrict__ addmat,
              void* __restrict__ Cv, int M, int N, int K, int mode)
{
    extern __shared__ uint32_t sm[];
    uint32_t* As = sm;                       // A tiles, u32 view (2 halves/u32)
    uint32_t* Bs = sm + STAGES * A_STAGE_U;  // B tiles (packed k-pairs)

    const int tid  = threadIdx.x;
    const int warp = tid >> 5;
    const int lane = tid & 31;
    const int wm   = (warp & 1) * 64;
    const int wn   = (warp >> 1) * 32;
    const int lg   = lane >> 2;
    const int lt   = lane & 3;
    const int bm   = blockIdx.y * BM;
    const int bn   = blockIdx.x * BN;

    // global->smem coords
    const int ar = tid >> 1;            // 0..127
    const int acb = (tid & 1) * 4;      // chunk base 0 or 4 (16B chunks)
    const int br = tid >> 3;            // 0..31
    const int bseg = (tid & 7) * 16;    // u32 segment base

    const __half* gA = A + (size_t)(bm + ar) * K;
    const uint32_t sAu = smem_u32(As);
    const uint32_t sBu = smem_u32(Bs);

    auto load_stage = [&](int slot, int k0) {
        uint32_t ab = sAu + (uint32_t)slot * (A_STAGE_U * 4);
        uint32_t bb = sBu + (uint32_t)slot * (B_STAGE_U * 4);
        const __half* a0 = gA + k0;
        const uint32_t* b0 = Bp + (size_t)(k0 / 2 + br) * N + bn + bseg;
        #pragma unroll
        for (int c = 0; c < 4; c++) {
            int ch = acb + c;           // 16B chunk index within row (0..7)
            CP_ASYNC16(ab + (uint32_t)(ar * (ASTU * 4) + ch * 16),
                       a0 + ch * 8);
            CP_ASYNC16(bb + (uint32_t)(br * (BSTU * 4) + (bseg + c * 4) * 4),
                       b0 + c * 4);
        }
    };

    uint32_t afr[2][4][4];
    uint32_t bfr[2][4][2];

    // chunk c covers k = 16c..16c+15
    auto load_frags = [&](uint32_t (*af)[4], uint32_t (*bf)[2],
                          const uint32_t* sA, const uint32_t* sB, int c) {
        #pragma unroll
        for (int i = 0; i < 4; i++) {
            const uint32_t* p = sA + (wm + i * 16 + lg) * ASTU + c * 8 + lt;
            af[i][0] = p[0];
            af[i][1] = p[8 * ASTU];
            af[i][2] = p[4];
            af[i][3] = p[8 * ASTU + 4];
        }
        #pragma unroll
        for (int j = 0; j < 4; j++) {
            const uint32_t* p = sB + (c * 8 + lt) * BSTU + wn + j * 8 + lg;
            bf[j][0] = p[0];
            bf[j][1] = p[4 * BSTU];
        }
    };

    float acc[4][4][4];
    #pragma unroll
    for (int i = 0; i < 4; i++)
        #pragma unroll
        for (int j = 0; j < 4; j++)
            #pragma unroll
            for (int q = 0; q < 4; q++) acc[i][j][q] = 0.0f;

    const int NT = K / BK;

    load_stage(0, 0);  CP_COMMIT();
    load_stage(1, BK); CP_COMMIT();
    CP_WAIT(1);
    __syncthreads();
    load_frags(afr[0], bfr[0], As, Bs, 0);

    for (int kt = 0; kt < NT; kt++) {
        if (kt + 2 < NT) load_stage((kt + 2) % STAGES, (kt + 2) * BK);
        CP_COMMIT();
        const uint32_t* cA = As + (kt % STAGES) * A_STAGE_U;
        const uint32_t* cB = Bs + (kt % STAGES) * B_STAGE_U;
        #pragma unroll
        for (int kk = 0; kk < 4; kk++) {
            const int cur = kk & 1;
            const int nxt = cur ^ 1;
            if (kk < 3) {
                load_frags(afr[nxt], bfr[nxt], cA, cB, kk + 1);
            } else if (kt + 1 < NT) {
                CP_WAIT(1);          // stage kt+1 resident
                __syncthreads();     // everyone done reading slot kt
                const uint32_t* nA = As + ((kt + 1) % STAGES) * A_STAGE_U;
                const uint32_t* nB = Bs + ((kt + 1) % STAGES) * B_STAGE_U;
                load_frags(afr[nxt], bfr[nxt], nA, nB, 0);
            }
            #pragma unroll
            for (int i = 0; i < 4; i++)
                #pragma unroll
                for (int j = 0; j < 4; j++)
                    MMA_F16(acc[i][j], afr[cur][i], bfr[cur][j]);
        }
    }

    // Epilogue
    #pragma unroll
    for (int i = 0; i < 4; i++) {
        #pragma unroll
        for (int j = 0; j < 4; j++) {
            const int r0 = bm + wm + i * 16 + lg;
            const int c0 = bn + wn + j * 8 + lt * 2;
            #pragma unroll
            for (int h = 0; h < 2; h++) {        // rows r0, r0+8
                const int r = r0 + h * 8;
                float vx = acc[i][j][h * 2 + 0];
                float vy = acc[i][j][h * 2 + 1];
                if (mode == 0) {
                    vx += bias[c0]; vy += bias[c0 + 1];
                    *(__half2*)((__half*)Cv + (size_t)r * N + c0) =
                        __floats2half2_rn(vx, vy);
                } else if (mode == 1) {
                    const __half2 ah = *(const __half2*)(addmat + (size_t)r * N + c0);
                    const float2 af2 = __half22float2(ah);
                    vx += af2.x; vy += af2.y;
                    *(__half2*)((__half*)Cv + (size_t)r * N + c0) =
                        __floats2half2_rn(vx, vy);
                } else if (mode == 2) {
                    vx = fmaxf(vx + bias[c0],     0.0f);
                    vy = fmaxf(vy + bias[c0 + 1], 0.0f);
                    *(__half2*)((__half*)Cv + (size_t)r * N + c0) =
                        __floats2half2_rn(vx, vy);
                } else {
                    vx = fmaxf(vx + bias[c0],     0.0f);
                    vy = fmaxf(vy + bias[c0 + 1], 0.0f);
                    *(float2*)((float*)Cv + (size_t)r * N + c0) = make_float2(vx, vy);
                }
            }
        }
    }
}

// ---------------------------------------------------------------------------
// 4) LSTM cell: gates from Z fp16; h -> fp16, c -> fp32
// ---------------------------------------------------------------------------
__global__ void lstm_cell(const __half* __restrict__ Z, int first)
{
    int idx = blockIdx.x * blockDim.x + threadIdx.x;
    if (idx >= BB * HDIM) return;
    int b = idx >> 11;
    int j = idx & 2047;
    const __half* zr = Z + (size_t)b * G4;
    float zi = __half2float(zr[j]);
    float zf = __half2float(zr[j + HDIM]);
    float zg = __half2float(zr[j + 2 * HDIM]);
    float zo = __half2float(zr[j + 3 * HDIM]);
    float ig = sigf(zi);
    float fg = sigf(zf);
    float gg = tanhf(zg);
    float og = sigf(zo);
    float cp = first ? 0.0f : g_c[idx];
    float cn = fg * cp + ig * gg;
    g_c[idx]  = cn;
    g_hh[idx] = __float2half(og * tanhf(cn));
}

// ---------------------------------------------------------------------------
// 5) Head: logits = A2 @ W3 + b3 (N=2), softmax
// ---------------------------------------------------------------------------
__global__ void head_kernel(const float* __restrict__ W3,
                            const float* __restrict__ b3,
                            float* __restrict__ out)
{
    int b = blockIdx.x;
    const float* a = g_A2 + (size_t)b * DIN;
    float p0 = 0.0f, p1 = 0.0f;
    for (int k = threadIdx.x; k < DIN; k += blockDim.x) {
        float av = a[k];
        p0 += av * W3[k * 2 + 0];
        p1 += av * W3[k * 2 + 1];
    }
    #pragma unroll
    for (int o = 16; o > 0; o >>= 1) {
        p0 += __shfl_down_sync(0xFFFFFFFFu, p0, o);
        p1 += __shfl_down_sync(0xFFFFFFFFu, p1, o);
    }
    __shared__ float r0[8], r1[8];
    int warp = threadIdx.x >> 5, lane = threadIdx.x & 31;
    if (lane == 0) { r0[warp] = p0; r1[warp] = p1; }
    __syncthreads();
    if (threadIdx.x == 0) {
        float l0 = b3[0], l1 = b3[1];
        #pragma unroll
        for (int w = 0; w < 8; w++) { l0 += r0[w]; l1 += r1[w]; }
        float m = fmaxf(l0, l1);
        float e0 = expf(l0 - m), e1 = expf(l1 - m);
        float inv = 1.0f / (e0 + e1);
        out[b * 2 + 0] = e0 * inv;
        out[b * 2 + 1] = e1 * inv;
    }
}

// ---------------------------------------------------------------------------
// Launch
// ---------------------------------------------------------------------------
extern "C" void kernel_launch(void* const* d_in, const int* in_sizes, int n_in,
                              void* d_out, int out_size)
{
    (void)in_sizes; (void)n_in; (void)out_size;
    const int*   path   = (const int*)  d_in[0];
    const float* emb    = (const float*)d_in[1];
    const float* W_lstm = (const float*)d_in[2];
    const float* U_lstm = (const float*)d_in[3];
    const float* b_lstm = (const float*)d_in[4];
    const float* W1     = (const float*)d_in[5];
    const float* b1     = (const float*)d_in[6];
    const float* W2     = (const float*)d_in[7];
    const float* b2     = (const float*)d_in[8];
    const float* W3     = (const float*)d_in[9];
    const float* b3     = (const float*)d_in[10];
    float* out = (float*)d_out;

    __half *Xh, *hh, *A1h, *XWh, *Zh;
    uint32_t *Wp, *Up, *W1p, *W2p;
    float *A2;
    cudaGetSymbolAddress((void**)&Xh,  g_Xh);
    cudaGetSymbolAddress((void**)&Wp,  g_Wp);
    cudaGetSymbolAddress((void**)&Up,  g_Up);
    cudaGetSymbolAddress((void**)&W1p, g_W1p);
    cudaGetSymbolAddress((void**)&W2p, g_W2p);
    cudaGetSymbolAddress((void**)&XWh, g_XWh);
    cudaGetSymbolAddress((void**)&Zh,  g_Zh);
    cudaGetSymbolAddress((void**)&hh,  g_hh);
    cudaGetSymbolAddress((void**)&A1h, g_A1h);
    cudaGetSymbolAddress((void**)&A2,  g_A2);

    cudaFuncSetAttribute(gemm_f16, cudaFuncAttributeMaxDynamicSharedMemorySize,
                         SMEM_BYTES);

    // 1) gather (fp16) + pack all weights to k-pair u32 layout
    gather_kernel<<<NSTEP * BB, 256>>>(path, emb);
    pack_w<<<((DIN / 2) * G4 + 255) / 256, 256>>>(W_lstm, Wp,  DIN,  G4);
    pack_w<<<((HDIM / 2) * G4 + 255) / 256, 256>>>(U_lstm, Up,  HDIM, G4);
    pack_w<<<((HDIM / 2) * DIN + 255) / 256, 256>>>(W1,    W1p, HDIM, DIN);
    pack_w<<<((DIN / 2) * DIN + 255) / 256, 256>>>(W2,     W2p, DIN,  DIN);

    // 2) XW = X @ W_lstm + b_lstm  (fp16 out; M=5120, N=8192, K=2048)
    gemm_f16<<<dim3(G4 / BN, (NSTEP * BB) / BM), 256, SMEM_BYTES>>>(
        Xh, Wp, b_lstm, nullptr, XWh, NSTEP * BB, G4, DIN, 0);

    // 3) step 0 (h=0): cell directly on XW[0] (fp16)
    lstm_cell<<<(BB * HDIM) / 256, 256>>>(XWh, 1);

    // 4) steps 1..4: Z = h @ U_lstm + XW[t] (fp16 in/out); then cell
    for (int t = 1; t < NSTEP; t++) {
        gemm_f16<<<dim3(G4 / BN, BB / BM), 256, SMEM_BYTES>>>(
            hh, Up, nullptr, XWh + (size_t)t * BB * G4, Zh, BB, G4, HDIM, 1);
        lstm_cell<<<(BB * HDIM) / 256, 256>>>(Zh, 0);
    }

    // 5) MLP: A1h = relu(h@W1+b1) fp16; A2 = relu(A1@W2+b2) fp32
    gemm_f16<<<dim3(DIN / BN, BB / BM), 256, SMEM_BYTES>>>(
        hh,  W1p, b1, nullptr, A1h, BB, DIN, HDIM, 2);
    gemm_f16<<<dim3(DIN / BN, BB / BM), 256, SMEM_BYTES>>>(
        A1h, W2p, b2, nullptr, A2,  BB, DIN, DIN, 3);

    // 6) head + softmax
    head_kernel<<<BB, 256>>>(W3, b3, out);
}